// round 3
// baseline (speedup 1.0000x reference)
#include <cuda_runtime.h>
#include <math.h>

// Problem constants (fixed shapes from reference)
#define CIN   256
#define COUT  512
#define HWSZ  3136          // 56*56
#define BATCH 32
#define NTOT  (BATCH*HWSZ)  // 100352 = 784 * 128
#define NGRP  32
#define CPG   (COUT/NGRP)   // 16 channels per group
#define GELEMS (CPG*HWSZ)   // 50176 elements per (b,g) group span
#define EPS_GN 1e-5f
#define HT_MIN -2.0f
#define HT_MAX  2.0f

// Per-(batch,group) statistics. Written fresh every launch -> deterministic.
__device__ float g_mean[BATCH*NGRP];
__device__ float g_rstd[BATCH*NGRP];

// ---------------------------------------------------------------------------
// Kernel 1: GEMM  y[b,o,hw] = sum_c W[o,c] * x[b,c,hw]
// Flattened N over (b,hw): n = b*HWSZ + hw, NTOT = 100352 = 784*128.
// Tile: BM=128 (cout) x BN=128 (n), BK=8. 256 threads, 8x8 micro-tile.
// Double-buffered smem: global loads for tile k+1 overlap FMAs on tile k.
// Since HWSZ % 8 == 0 and fragments are 8-aligned in n, every vector
// load/store stays within a single batch -> contiguous addresses.
// ---------------------------------------------------------------------------
#define BM 128
#define BN 128
#define BK 8

__global__ __launch_bounds__(256, 2)
void gemm_kernel(const float* __restrict__ x,
                 const float* __restrict__ W,
                 float* __restrict__ y)
{
    __shared__ float As[2][BK][BM + 4];   // +4 pad keeps float4 alignment, breaks store conflicts
    __shared__ float Bs[2][BK][BN];

    const int tid = threadIdx.x;
    const int m0 = blockIdx.y * BM;
    const int n0 = blockIdx.x * BN;
    const int tx = tid & 15;           // 0..15 -> n micro-tile
    const int ty = tid >> 4;           // 0..15 -> m micro-tile

    // A (weight) load mapping: 128 rows x 8 cols per tile, float4/thread
    const int a_o = tid >> 1;          // 0..127
    const int a_c = (tid & 1) * 4;     // 0 or 4
    const float* wptr = W + (size_t)(m0 + a_o) * CIN + a_c;

    // B (x) load mapping: 8 rows(c) x 128 cols(n), float4/thread
    const int b_c = tid >> 5;          // 0..7
    const int b_n = (tid & 31) * 4;    // 0..124
    const int nB  = n0 + b_n;
    const int bbB = nB / HWSZ;         // batch of this thread's B column
    const int hwB = nB - bbB * HWSZ;
    const float* xptr = x + ((size_t)bbB * CIN + b_c) * HWSZ + hwB;

    float acc[8][8];
    #pragma unroll
    for (int i = 0; i < 8; i++)
        #pragma unroll
        for (int j = 0; j < 8; j++)
            acc[i][j] = 0.0f;

    // ---- prologue: load tile 0 into buffer 0 ----
    {
        float4 av = *(const float4*)(wptr);
        As[0][a_c + 0][a_o] = av.x;
        As[0][a_c + 1][a_o] = av.y;
        As[0][a_c + 2][a_o] = av.z;
        As[0][a_c + 3][a_o] = av.w;
        float4 bv = *(const float4*)(xptr);
        *(float4*)&Bs[0][b_c][b_n] = bv;
    }
    __syncthreads();

    int cur = 0;
    for (int k0 = 0; k0 < CIN; k0 += BK) {
        float4 av, bv;
        const bool more = (k0 + BK) < CIN;
        if (more) {
            av = *(const float4*)(wptr + (k0 + BK));
            bv = *(const float4*)(xptr + (size_t)(k0 + BK) * HWSZ);
        }

        #pragma unroll
        for (int kk = 0; kk < BK; kk++) {
            float a[8], b[8];
            *(float4*)(a + 0) = *(const float4*)&As[cur][kk][ty * 8 + 0];
            *(float4*)(a + 4) = *(const float4*)&As[cur][kk][ty * 8 + 4];
            *(float4*)(b + 0) = *(const float4*)&Bs[cur][kk][tx * 8 + 0];
            *(float4*)(b + 4) = *(const float4*)&Bs[cur][kk][tx * 8 + 4];
            #pragma unroll
            for (int i = 0; i < 8; i++)
                #pragma unroll
                for (int j = 0; j < 8; j++)
                    acc[i][j] = fmaf(a[i], b[j], acc[i][j]);
        }

        if (more) {
            const int nxt = cur ^ 1;
            As[nxt][a_c + 0][a_o] = av.x;
            As[nxt][a_c + 1][a_o] = av.y;
            As[nxt][a_c + 2][a_o] = av.z;
            As[nxt][a_c + 3][a_o] = av.w;
            *(float4*)&Bs[nxt][b_c][b_n] = bv;
        }
        __syncthreads();
        cur ^= 1;
    }

    // --- epilogue: write 8x8 fragment. 8 consecutive n stay in one batch ---
    const int nc  = n0 + tx * 8;
    const int bb2 = nc / HWSZ;
    const int hw2 = nc - bb2 * HWSZ;
    #pragma unroll
    for (int i = 0; i < 8; i++) {
        float* yp = y + ((size_t)bb2 * COUT + (m0 + ty * 8 + i)) * HWSZ + hw2;
        *(float4*)(yp + 0) = make_float4(acc[i][0], acc[i][1], acc[i][2], acc[i][3]);
        *(float4*)(yp + 4) = make_float4(acc[i][4], acc[i][5], acc[i][6], acc[i][7]);
    }
}

// ---------------------------------------------------------------------------
// Kernel 2: GroupNorm statistics. One block per (b,g).
// Channels of a group are contiguous in y -> one 50176-float span.
// ---------------------------------------------------------------------------
__global__ __launch_bounds__(256)
void stats_kernel(const float* __restrict__ y)
{
    const int bg = blockIdx.x;                      // b*NGRP + g
    const float4* p = (const float4*)(y + (size_t)bg * GELEMS);
    const int n4 = GELEMS / 4;                      // 12544

    float s = 0.0f, ss = 0.0f;
    for (int i = threadIdx.x; i < n4; i += 256) {
        float4 v = p[i];
        s  += (v.x + v.y) + (v.z + v.w);
        ss += (v.x * v.x + v.y * v.y) + (v.z * v.z + v.w * v.w);
    }

    // warp reduce
    #pragma unroll
    for (int o = 16; o > 0; o >>= 1) {
        s  += __shfl_down_sync(0xffffffffu, s, o);
        ss += __shfl_down_sync(0xffffffffu, ss, o);
    }
    __shared__ float ws[8], wss[8];
    const int lane = threadIdx.x & 31, wid = threadIdx.x >> 5;
    if (lane == 0) { ws[wid] = s; wss[wid] = ss; }
    __syncthreads();
    if (wid == 0) {
        s  = (lane < 8) ? ws[lane]  : 0.0f;
        ss = (lane < 8) ? wss[lane] : 0.0f;
        #pragma unroll
        for (int o = 4; o > 0; o >>= 1) {
            s  += __shfl_down_sync(0xffffffffu, s, o);
            ss += __shfl_down_sync(0xffffffffu, ss, o);
        }
        if (lane == 0) {
            const float inv_n = 1.0f / (float)GELEMS;
            float mean = s * inv_n;
            float var  = ss * inv_n - mean * mean;
            g_mean[bg] = mean;
            g_rstd[bg] = rsqrtf(var + EPS_GN);
        }
    }
}

// ---------------------------------------------------------------------------
// Kernel 3: normalize + affine + hardtanh, in place, float4.
// idx = (b*NGRP+g)*GELEMS + (o%CPG)*HWSZ + hw ; HWSZ%4==0 so one float4
// shares a single (bg, o).
// ---------------------------------------------------------------------------
__global__ __launch_bounds__(256)
void norm_kernel(float* __restrict__ y,
                 const float* __restrict__ gamma,
                 const float* __restrict__ beta)
{
    const size_t i4  = (size_t)blockIdx.x * 256 + threadIdx.x;
    const size_t idx = i4 * 4;
    const int o  = (int)((idx / HWSZ) % COUT);
    const int bg = (int)(idx / GELEMS);

    const float r  = g_rstd[bg];
    const float ga = gamma[o] * r;
    const float be = beta[o] - g_mean[bg] * ga;

    float4 v = *(float4*)(y + idx);
    v.x = fminf(fmaxf(fmaf(v.x, ga, be), HT_MIN), HT_MAX);
    v.y = fminf(fmaxf(fmaf(v.y, ga, be), HT_MIN), HT_MAX);
    v.z = fminf(fmaxf(fmaf(v.z, ga, be), HT_MIN), HT_MAX);
    v.w = fminf(fmaxf(fmaf(v.w, ga, be), HT_MIN), HT_MAX);
    *(float4*)(y + idx) = v;
}

// ---------------------------------------------------------------------------
extern "C" void kernel_launch(void* const* d_in, const int* in_sizes, int n_in,
                              void* d_out, int out_size)
{
    const float* x     = (const float*)d_in[0];  // [32,256,56,56]
    const float* W     = (const float*)d_in[1];  // [512,256]
    const float* gamma = (const float*)d_in[2];  // [512]
    const float* beta  = (const float*)d_in[3];  // [512]
    float* y = (float*)d_out;                    // [32,512,56,56]

    // 1) GEMM -> d_out
    dim3 ggrid(NTOT / BN, COUT / BM);            // (784, 4)
    gemm_kernel<<<ggrid, 256>>>(x, W, y);

    // 2) group statistics
    stats_kernel<<<BATCH * NGRP, 256>>>(y);

    // 3) normalize + clamp in place
    const size_t total4 = (size_t)BATCH * COUT * HWSZ / 4;   // 12,845,056
    norm_kernel<<<(unsigned)(total4 / 256), 256>>>(y, gamma, beta);
}